// round 1
// baseline (speedup 1.0000x reference)
#include <cuda_runtime.h>
#include <math.h>

// Problem constants
#define LL   1024
#define DMM  128
#define HH   4
#define DH_  32
#define QP_  4
#define VP_  4
#define DP_  64

// Scratch (static device globals; allocation-free)
__device__ float g_Ahat[LL * HH * 44];   // [Q*scale, w*Qg] per (i,h)
__device__ float g_Bhat[LL * HH * 44];   // [K, Kg]        per (j,h)
__device__ float g_ci[HH * LL];          // -0.5*w*|Qg|^2
__device__ float g_cj[HH * LL];          // -0.5*w*|Kg|^2
__device__ float g_V [LL * 128];         // V[i][h*32+d]
__device__ float g_Vg[LL * 48];          // Vg[i][h*12+k]
__device__ float g_attn[(size_t)HH * LL * LL]; // attn[h][i][j]
__device__ float g_os  [LL * 128];       // o_s
__device__ float g_optg[LL * 48];        // o_pt_g
__device__ float g_opair[LL * 256];      // o_pair

// ---------------------------------------------------------------------------
// Kernel P: layernorm + all projections + frame transforms. grid=128, blk=128
// Each block processes 8 rows.
// ---------------------------------------------------------------------------
__global__ __launch_bounds__(128) void kprep(
    const float* __restrict__ single, const float* __restrict__ T,
    const float* __restrict__ w_C,    const float* __restrict__ ln_g,
    const float* __restrict__ ln_b,
    const float* __restrict__ Wq, const float* __restrict__ Wk,
    const float* __restrict__ Wv, const float* __restrict__ Wqpt,
    const float* __restrict__ Wkpt, const float* __restrict__ Wvpt)
{
    __shared__ float zs[8][128];
    __shared__ float proj[8][528];
    __shared__ float red[2][4];

    const int tid = threadIdx.x;
    const int i0  = blockIdx.x * 8;
    const int lane = tid & 31, wid = tid >> 5;

    // Layernorm per row
    for (int r = 0; r < 8; r++) {
        float x = single[(i0 + r) * 128 + tid];
        float s = x, s2 = x * x;
        #pragma unroll
        for (int o = 16; o; o >>= 1) {
            s  += __shfl_xor_sync(0xffffffffu, s,  o);
            s2 += __shfl_xor_sync(0xffffffffu, s2, o);
        }
        if (lane == 0) { red[0][wid] = s; red[1][wid] = s2; }
        __syncthreads();
        float sum  = red[0][0] + red[0][1] + red[0][2] + red[0][3];
        float sum2 = red[1][0] + red[1][1] + red[1][2] + red[1][3];
        float mu  = sum * (1.f / 128.f);
        float var = sum2 * (1.f / 128.f) - mu * mu;
        float inv = rsqrtf(var + 1e-5f);
        zs[r][tid] = (x - mu) * inv * ln_g[tid] + ln_b[tid];
        __syncthreads();
    }

    // Projections: 528 outputs per row. proj layout: Q 0, K 128, V 256,
    // Qpt 384, Kpt 432, Vpt 480.
    for (int o = tid; o < 528; o += 128) {
        const float* W; int col, ow;
        if      (o < 128) { W = Wq;   col = o;       ow = 128; }
        else if (o < 256) { W = Wk;   col = o - 128; ow = 128; }
        else if (o < 384) { W = Wv;   col = o - 256; ow = 128; }
        else if (o < 432) { W = Wqpt; col = o - 384; ow = 48;  }
        else if (o < 480) { W = Wkpt; col = o - 432; ow = 48;  }
        else              { W = Wvpt; col = o - 480; ow = 48;  }
        float acc[8] = {0,0,0,0,0,0,0,0};
        for (int d = 0; d < 128; d++) {
            float w = W[d * ow + col];
            #pragma unroll
            for (int r = 0; r < 8; r++) acc[r] += zs[r][d] * w;
        }
        #pragma unroll
        for (int r = 0; r < 8; r++) proj[r][o] = acc[r];
    }
    __syncthreads();

    // Copy Q (scaled), K, V into global scratch
    const float scale = 0.17677669529663687f;  // 1/sqrt(32)
    for (int u = tid; u < 1024; u += 128) {
        int r = u >> 7, k = u & 127;
        int i = i0 + r; int h = k >> 5, d = k & 31;
        g_Ahat[(i * 4 + h) * 44 + d] = proj[r][k] * scale;
        g_Bhat[(i * 4 + h) * 44 + d] = proj[r][128 + k];
        g_V[i * 128 + k] = proj[r][256 + k];
    }

    // Frame transforms: one thread per (row, head)
    if (tid < 32) {
        int r = tid >> 2, h = tid & 3;
        int i = i0 + r;
        float w = log1pf(__expf(w_C[h]));
        float R[3][3], tv[3];
        #pragma unroll
        for (int x = 0; x < 3; x++) {
            #pragma unroll
            for (int y = 0; y < 3; y++) R[x][y] = T[i * 16 + x * 4 + y];
            tv[x] = T[i * 16 + x * 4 + 3];
        }
        float qq = 0.f, kk = 0.f;
        #pragma unroll
        for (int p = 0; p < 4; p++) {
            float q0 = proj[r][384 + h * 12 + p * 3 + 0];
            float q1 = proj[r][384 + h * 12 + p * 3 + 1];
            float q2 = proj[r][384 + h * 12 + p * 3 + 2];
            float k0 = proj[r][432 + h * 12 + p * 3 + 0];
            float k1 = proj[r][432 + h * 12 + p * 3 + 1];
            float k2 = proj[r][432 + h * 12 + p * 3 + 2];
            float v0 = proj[r][480 + h * 12 + p * 3 + 0];
            float v1 = proj[r][480 + h * 12 + p * 3 + 1];
            float v2 = proj[r][480 + h * 12 + p * 3 + 2];
            #pragma unroll
            for (int x = 0; x < 3; x++) {
                float gq = R[x][0] * q0 + R[x][1] * q1 + R[x][2] * q2 + tv[x];
                float gk = R[x][0] * k0 + R[x][1] * k1 + R[x][2] * k2 + tv[x];
                float gv = R[x][0] * v0 + R[x][1] * v1 + R[x][2] * v2 + tv[x];
                g_Ahat[(i * 4 + h) * 44 + 32 + p * 3 + x] = w * gq;
                g_Bhat[(i * 4 + h) * 44 + 32 + p * 3 + x] = gk;
                g_Vg[i * 48 + h * 12 + p * 3 + x] = gv;
                qq += gq * gq; kk += gk * gk;
            }
        }
        g_ci[h * 1024 + i] = -0.5f * w * qq;
        g_cj[h * 1024 + i] = -0.5f * w * kk;
    }
}

// ---------------------------------------------------------------------------
// Kernel M: per-row logits + softmax + o_pair. grid=1024 (one row), blk=256
// Pair row streamed once from DRAM; second pass expected to hit L2.
// ---------------------------------------------------------------------------
__global__ __launch_bounds__(256) void kmain(
    const float* __restrict__ pair, const float* __restrict__ Wb)
{
    __shared__ float probs[4][1024];
    __shared__ float Ahat_s[176];
    __shared__ float Wb_s[256];
    __shared__ float ci_s[4];
    __shared__ float redm[8][4];
    __shared__ float reds[8][4];
    __shared__ float partial[4][4][64];

    const int tid = threadIdx.x;
    const int i   = blockIdx.x;
    const int lane = tid & 31, wid = tid >> 5;

    if (tid < 176) Ahat_s[tid] = g_Ahat[i * 176 + tid];
    if (tid < 256) Wb_s[tid] = Wb[tid];
    if (tid < 4)   ci_s[tid] = g_ci[tid * 1024 + i];
    __syncthreads();

    const float* prow = pair + (size_t)i * 65536;

    // Pass 1: logits
    for (int jj = 0; jj < 4; jj++) {
        int j = jj * 256 + tid;
        float bh[4] = {0,0,0,0};
        const float4* p4 = (const float4*)(prow + (size_t)j * 64);
        #pragma unroll
        for (int c4 = 0; c4 < 16; c4++) {
            float4 v = p4[c4];
            const float* wb = Wb_s + c4 * 16;
            #pragma unroll
            for (int h = 0; h < 4; h++)
                bh[h] += v.x * wb[h] + v.y * wb[4 + h] + v.z * wb[8 + h] + v.w * wb[12 + h];
        }
        #pragma unroll
        for (int h = 0; h < 4; h++) {
            const float4* b4 = (const float4*)(g_Bhat + ((size_t)j * 4 + h) * 44);
            const float* A = Ahat_s + h * 44;
            float acc = 0.f;
            #pragma unroll
            for (int k4 = 0; k4 < 11; k4++) {
                float4 v = b4[k4];
                acc += v.x * A[k4 * 4] + v.y * A[k4 * 4 + 1]
                     + v.z * A[k4 * 4 + 2] + v.w * A[k4 * 4 + 3];
            }
            probs[h][j] = acc + bh[h] + ci_s[h] + g_cj[h * 1024 + j];
        }
    }
    __syncthreads();

    // Softmax: max
    #pragma unroll
    for (int h = 0; h < 4; h++) {
        float m = -1e30f;
        #pragma unroll
        for (int jj = 0; jj < 4; jj++) m = fmaxf(m, probs[h][jj * 256 + tid]);
        #pragma unroll
        for (int o = 16; o; o >>= 1) m = fmaxf(m, __shfl_xor_sync(0xffffffffu, m, o));
        if (lane == 0) redm[wid][h] = m;
    }
    __syncthreads();
    float mx[4];
    #pragma unroll
    for (int h = 0; h < 4; h++) {
        float m = redm[0][h];
        #pragma unroll
        for (int w = 1; w < 8; w++) m = fmaxf(m, redm[w][h]);
        mx[h] = m;
    }
    // exp + sum
    #pragma unroll
    for (int h = 0; h < 4; h++) {
        float s = 0.f;
        #pragma unroll
        for (int jj = 0; jj < 4; jj++) {
            int j = jj * 256 + tid;
            float e = __expf(probs[h][j] - mx[h]);
            probs[h][j] = e;
            s += e;
        }
        #pragma unroll
        for (int o = 16; o; o >>= 1) s += __shfl_xor_sync(0xffffffffu, s, o);
        if (lane == 0) reds[wid][h] = s;
    }
    __syncthreads();
    float inv[4];
    #pragma unroll
    for (int h = 0; h < 4; h++) {
        float s = 0.f;
        #pragma unroll
        for (int w = 0; w < 8; w++) s += reds[w][h];
        inv[h] = 1.0f / s;
    }
    // normalize + write attn
    #pragma unroll
    for (int jj = 0; jj < 4; jj++) {
        int j = jj * 256 + tid;
        #pragma unroll
        for (int h = 0; h < 4; h++) {
            float pv = probs[h][j] * inv[h];
            probs[h][j] = pv;
            g_attn[((size_t)h * 1024 + i) * 1024 + j] = pv;
        }
    }
    __syncthreads();

    // Pass 2: o_pair (pair row re-read, L2 hit)
    const int c = tid & 63, grp = tid >> 6;
    float acc[4] = {0,0,0,0};
    for (int j = grp; j < 1024; j += 4) {
        float p = prow[(size_t)j * 64 + c];
        #pragma unroll
        for (int h = 0; h < 4; h++) acc[h] += p * probs[h][j];
    }
    #pragma unroll
    for (int h = 0; h < 4; h++) partial[grp][h][c] = acc[h];
    __syncthreads();
    {
        int h = tid >> 6, cc = tid & 63;
        float s = partial[0][h][cc] + partial[1][h][cc]
                + partial[2][h][cc] + partial[3][h][cc];
        g_opair[i * 256 + h * 64 + cc] = s;
    }
}

// ---------------------------------------------------------------------------
// Kernel S: o_s = attn@V, o_pt_g = attn@Vg. grid = 64 i-tiles x 4 heads = 256,
// blk = 256. Tiny GEMM N=44, K=1024 per head.
// ---------------------------------------------------------------------------
__global__ __launch_bounds__(256) void kattnv()
{
    __shared__ float As[16][129];
    __shared__ float Vs[128][45];

    const int h  = blockIdx.x & 3;
    const int i0 = (blockIdx.x >> 2) * 16;
    const int tid = threadIdx.x;
    const int r  = tid & 15;
    const int nb = tid >> 4;       // 0..15
    const int n2 = nb + 32;

    float acc0 = 0.f, acc1 = 0.f, acc2 = 0.f;

    for (int j0 = 0; j0 < 1024; j0 += 128) {
        __syncthreads();
        if (tid < 128) {
            int jj = tid;
            const float4* vp = (const float4*)(g_V + (size_t)(j0 + jj) * 128 + h * 32);
            #pragma unroll
            for (int q = 0; q < 8; q++) {
                float4 v = vp[q];
                Vs[jj][q * 4 + 0] = v.x; Vs[jj][q * 4 + 1] = v.y;
                Vs[jj][q * 4 + 2] = v.z; Vs[jj][q * 4 + 3] = v.w;
            }
            const float4* gp = (const float4*)(g_Vg + (size_t)(j0 + jj) * 48 + h * 12);
            #pragma unroll
            for (int q = 0; q < 3; q++) {
                float4 v = gp[q];
                Vs[jj][32 + q * 4 + 0] = v.x; Vs[jj][32 + q * 4 + 1] = v.y;
                Vs[jj][32 + q * 4 + 2] = v.z; Vs[jj][32 + q * 4 + 3] = v.w;
            }
        } else {
            int t2 = tid - 128;
            for (int u = t2; u < 2048; u += 128) {
                int rr = u >> 7, jj = u & 127;
                As[rr][jj] = g_attn[((size_t)h * 1024 + (i0 + rr)) * 1024 + j0 + jj];
            }
        }
        __syncthreads();
        #pragma unroll 8
        for (int jj = 0; jj < 128; jj++) {
            float a = As[r][jj];
            acc0 += a * Vs[jj][nb];
            acc1 += a * Vs[jj][nb + 16];
            acc2 += a * Vs[jj][n2];   // garbage for n2>=44, never stored
        }
    }
    int i = i0 + r;
    g_os[i * 128 + h * 32 + nb]      = acc0;
    g_os[i * 128 + h * 32 + nb + 16] = acc1;
    if (n2 < 44) g_optg[i * 48 + h * 12 + (n2 - 32)] = acc2;
}

// ---------------------------------------------------------------------------
// Kernel F: o_pt rotation+norm, concat, out = single + f@Wout + b_out.
// grid=128 (8 rows/block), blk=128.
// ---------------------------------------------------------------------------
__global__ __launch_bounds__(128) void kfinal(
    const float* __restrict__ single, const float* __restrict__ T,
    const float* __restrict__ Wout,   const float* __restrict__ b_out,
    float* __restrict__ out)
{
    __shared__ float fs[8][448];
    const int tid = threadIdx.x;
    const int i0  = blockIdx.x * 8;

    for (int u = tid; u < 1024; u += 128) {
        int r = u >> 7, k = u & 127;
        fs[r][k] = g_os[(i0 + r) * 128 + k];
    }
    for (int u = tid; u < 2048; u += 128) {
        int r = u >> 8, k = u & 255;
        fs[r][128 + k] = g_opair[(i0 + r) * 256 + k];
    }
    {
        int r = tid >> 4, hp = tid & 15, h = hp >> 2, p = hp & 3;
        int i = i0 + r;
        float Rm[3][3], tv[3];
        #pragma unroll
        for (int y = 0; y < 3; y++) {
            #pragma unroll
            for (int x = 0; x < 3; x++) Rm[y][x] = T[i * 16 + y * 4 + x];
            tv[y] = T[i * 16 + y * 4 + 3];
        }
        float g0 = g_optg[i * 48 + h * 12 + p * 3 + 0] - tv[0];
        float g1 = g_optg[i * 48 + h * 12 + p * 3 + 1] - tv[1];
        float g2 = g_optg[i * 48 + h * 12 + p * 3 + 2] - tv[2];
        float nrm = 0.f;
        #pragma unroll
        for (int x = 0; x < 3; x++) {
            float v = Rm[0][x] * g0 + Rm[1][x] * g1 + Rm[2][x] * g2;
            fs[r][384 + h * 12 + p * 3 + x] = v;
            nrm += v * v;
        }
        fs[r][432 + h * 4 + p] = sqrtf(nrm);
    }
    __syncthreads();

    float acc[8] = {0,0,0,0,0,0,0,0};
    for (int k = 0; k < 448; k++) {
        float w = Wout[k * 128 + tid];
        #pragma unroll
        for (int r = 0; r < 8; r++) acc[r] += fs[r][k] * w;
    }
    float bo = b_out[tid];
    #pragma unroll
    for (int r = 0; r < 8; r++)
        out[(i0 + r) * 128 + tid] = single[(i0 + r) * 128 + tid] + acc[r] + bo;
}

// ---------------------------------------------------------------------------
extern "C" void kernel_launch(void* const* d_in, const int* in_sizes, int n_in,
                              void* d_out, int out_size)
{
    const float* single = (const float*)d_in[0];
    const float* pair   = (const float*)d_in[1];
    const float* T      = (const float*)d_in[2];
    const float* w_C    = (const float*)d_in[3];
    const float* ln_g   = (const float*)d_in[4];
    const float* ln_b   = (const float*)d_in[5];
    const float* Wq     = (const float*)d_in[6];
    const float* Wk     = (const float*)d_in[7];
    const float* Wv     = (const float*)d_in[8];
    const float* Wqpt   = (const float*)d_in[9];
    const float* Wkpt   = (const float*)d_in[10];
    const float* Wvpt   = (const float*)d_in[11];
    const float* Wb     = (const float*)d_in[12];
    const float* Wout   = (const float*)d_in[13];
    const float* b_out  = (const float*)d_in[14];
    float* out = (float*)d_out;

    kprep<<<128, 128>>>(single, T, w_C, ln_g, ln_b, Wq, Wk, Wv, Wqpt, Wkpt, Wvpt);
    kmain<<<1024, 256>>>(pair, Wb);
    kattnv<<<256, 256>>>();
    kfinal<<<128, 128>>>(single, T, Wout, b_out, out);
}